// round 1
// baseline (speedup 1.0000x reference)
#include <cuda_runtime.h>
#include <cuda_bf16.h>
#include <cstdint>

#define BB 4
#define NN 16384
#define MM 16384
#define HH 32
#define KK 15
#define FF 64
#define CC 64
#define TPB 16      // points per block
#define THREADS 512 // 16 warps, 1 warp per point in phase A

// smem layout sizes (floats)
#define WF_ELEMS   (TPB * KK * FF)   // 16*960 = 15360
#define WSM_ELEMS  (TPB * HH * KK)   // 16*480 = 7680
#define IDX_ELEMS  (TPB * HH)        // 512 (ints)
#define KP_ELEMS   (KK * 3)          // 45

__global__ void __launch_bounds__(THREADS, 2)
kpconv_kernel(const float* __restrict__ points,
              const float* __restrict__ features,
              const float* __restrict__ output_points,
              const float* __restrict__ k_points,
              const float* __restrict__ k_values,
              const int*   __restrict__ neighbor_indices,
              float*       __restrict__ out)
{
    extern __shared__ float smem[];
    float* wf   = smem;                       // [TPB][KK*FF]
    float* wsm  = wf + WF_ELEMS;              // [TPB][HH*KK]
    int*   idxs = (int*)(wsm + WSM_ELEMS);    // [TPB][HH]
    float* kps  = (float*)(idxs + IDX_ELEMS); // [KK*3]

    const int tid  = threadIdx.x;
    const int warp = tid >> 5;
    const int lane = tid & 31;

    if (tid < KP_ELEMS) kps[tid] = k_points[tid];
    __syncthreads();

    // ---------------- Phase A: per-warp point, compute w then wf ----------
    const int gp = blockIdx.x * TPB + warp;     // global output-point id in [0, B*M)
    const int b  = gp >> 14;                    // / MM
    const float ox = output_points[gp * 3 + 0];
    const float oy = output_points[gp * 3 + 1];
    const float oz = output_points[gp * 3 + 2];

    // lane = neighbor h
    const int nidx = neighbor_indices[gp * HH + lane];
    idxs[warp * HH + lane] = nidx;
    const float* pp = points + ((size_t)b * NN + nidx) * 3;
    const float rx = pp[0] - ox;
    const float ry = pp[1] - oy;
    const float rz = pp[2] - oz;

    float* wrow_mine = wsm + warp * (HH * KK) + lane * KK;
    #pragma unroll
    for (int k = 0; k < KK; k++) {
        const float dx = rx - kps[k * 3 + 0];
        const float dy = ry - kps[k * 3 + 1];
        const float dz = rz - kps[k * 3 + 2];
        const float d  = sqrtf(fmaf(dx, dx, fmaf(dy, dy, dz * dz)));
        wrow_mine[k] = fmaxf(1.0f - d, 0.0f);   // EXTENT = 1.0
    }
    __syncwarp();

    // lane handles feature columns f0 = lane, f1 = lane+32
    float acc0[KK], acc1[KK];
    #pragma unroll
    for (int k = 0; k < KK; k++) { acc0[k] = 0.0f; acc1[k] = 0.0f; }

    const float* fbase = features + (size_t)b * NN * FF;
    const int* idxw = idxs + warp * HH;
    const float* wbase = wsm + warp * (HH * KK);

    #pragma unroll 2
    for (int h = 0; h < HH; h++) {
        const int ni = idxw[h];
        const float* frow = fbase + (size_t)ni * FF;
        const float fa = __ldg(frow + lane);
        const float fb = __ldg(frow + lane + 32);
        const float* wrow = wbase + h * KK;   // broadcast LDS across lanes
        #pragma unroll
        for (int k = 0; k < KK; k++) {
            const float w = wrow[k];
            acc0[k] = fmaf(w, fa, acc0[k]);
            acc1[k] = fmaf(w, fb, acc1[k]);
        }
    }

    // store wf[warp][k][f]
    float* wfp = wf + warp * (KK * FF);
    #pragma unroll
    for (int k = 0; k < KK; k++) {
        wfp[k * FF + lane]      = acc0[k];
        wfp[k * FF + lane + 32] = acc1[k];
    }
    __syncthreads();

    // ---------------- Phase B: out[TPB][CC] = wf[TPB][K*F] @ kv[K*F][CC] ---
    const int c  = tid & 63;
    const int pq = tid >> 6;        // 0..7 ; handles points pq and pq+8
    const float* wf0 = wf + pq * (KK * FF);
    const float* wf1 = wf + (pq + 8) * (KK * FF);

    float o0 = 0.0f, o1 = 0.0f;
    const float* kvc = k_values + c;

    #pragma unroll 4
    for (int kf = 0; kf < KK * FF; kf += 4) {
        const float4 a0 = *(const float4*)(wf0 + kf);   // broadcast 16B LDS
        const float4 a1 = *(const float4*)(wf1 + kf);
        const float kv0 = __ldg(kvc + (size_t)(kf + 0) * CC);
        const float kv1 = __ldg(kvc + (size_t)(kf + 1) * CC);
        const float kv2 = __ldg(kvc + (size_t)(kf + 2) * CC);
        const float kv3 = __ldg(kvc + (size_t)(kf + 3) * CC);
        o0 = fmaf(a0.x, kv0, o0);  o1 = fmaf(a1.x, kv0, o1);
        o0 = fmaf(a0.y, kv1, o0);  o1 = fmaf(a1.y, kv1, o1);
        o0 = fmaf(a0.z, kv2, o0);  o1 = fmaf(a1.z, kv2, o1);
        o0 = fmaf(a0.w, kv3, o0);  o1 = fmaf(a1.w, kv3, o1);
    }

    const size_t obase = (size_t)blockIdx.x * TPB;
    out[(obase + pq)     * CC + c] = o0;
    out[(obase + pq + 8) * CC + c] = o1;
}

extern "C" void kernel_launch(void* const* d_in, const int* in_sizes, int n_in,
                              void* d_out, int out_size)
{
    const float* points         = (const float*)d_in[0];
    const float* features       = (const float*)d_in[1];
    const float* output_points  = (const float*)d_in[2];
    const float* k_points       = (const float*)d_in[3];
    const float* k_values       = (const float*)d_in[4];
    const int*   neighbor_idx   = (const int*)d_in[5];
    float* out = (float*)d_out;

    const int smem_bytes = (WF_ELEMS + WSM_ELEMS) * sizeof(float)
                         + IDX_ELEMS * sizeof(int)
                         + (KP_ELEMS + 3) * sizeof(float);

    cudaFuncSetAttribute(kpconv_kernel,
                         cudaFuncAttributeMaxDynamicSharedMemorySize, smem_bytes);

    const int total_points = BB * MM;            // 65536
    const int blocks = total_points / TPB;       // 4096
    kpconv_kernel<<<blocks, THREADS, smem_bytes>>>(
        points, features, output_points, k_points, k_values, neighbor_idx, out);
}

// round 3
// speedup vs baseline: 2.0323x; 2.0323x over previous
#include <cuda_runtime.h>
#include <cuda_bf16.h>
#include <cstdint>

#define BB 4
#define NN 16384
#define MM 16384
#define HH 32
#define KK 15
#define FF 64
#define CC 64
#define KF 960
#define TOTALP (BB * MM)      // 65536

// ---------------- Phase-A config ----------------
#define TPB 16
#define THREADS_A 512

// ---------------- GEMM config -------------------
#define PTS_CTA 256           // points per CTA
#define THREADS_G 256         // 8 warps, 32 points each
#define KCH 64                // bf16 K-elements per chunk
#define NCH (KF / KCH)        // 15
#define ROWB 144              // smem row stride bytes (72 bf16) -> conflict-free frags

// smem byte offsets (GEMM kernel)
#define OFF_WFHI 0
#define OFF_WFLO (PTS_CTA * ROWB)             // 36864
#define OFF_KVHI (2 * PTS_CTA * ROWB)         // 73728
#define OFF_KVLO (OFF_KVHI + CC * ROWB)       // 82944
#define SMEM_G   (OFF_KVLO + CC * ROWB)       // 92160

// ------------- device scratch -------------
__device__ __nv_bfloat16 g_WFhi[(size_t)TOTALP * KF];
__device__ __nv_bfloat16 g_WFlo[(size_t)TOTALP * KF];
__device__ __nv_bfloat16 g_KVThi[CC * KF];    // [c][kf] row-major
__device__ __nv_bfloat16 g_KVTlo[CC * KF];

// ------------- helpers -------------
__device__ __forceinline__ uint32_t smem_u32(const void* p) {
    uint32_t a;
    asm("{ .reg .u64 t; cvta.to.shared.u64 t, %1; cvt.u32.u64 %0, t; }" : "=r"(a) : "l"(p));
    return a;
}
__device__ __forceinline__ void cpasync16(uint32_t dst, const void* src) {
    asm volatile("cp.async.cg.shared.global [%0], [%1], 16;" :: "r"(dst), "l"(src));
}
__device__ __forceinline__ void cpasync_commit() { asm volatile("cp.async.commit_group;"); }
__device__ __forceinline__ void cpasync_wait0()  { asm volatile("cp.async.wait_group 0;" ::: "memory"); }
__device__ __forceinline__ uint32_t lds32(uint32_t a) {
    uint32_t v; asm volatile("ld.shared.b32 %0, [%1];" : "=r"(v) : "r"(a)); return v;
}
__device__ __forceinline__ void mma16816(float* c, const uint32_t* a, const uint32_t* b) {
    asm volatile(
        "mma.sync.aligned.m16n8k16.row.col.f32.bf16.bf16.f32 "
        "{%0,%1,%2,%3}, {%4,%5,%6,%7}, {%8,%9}, {%0,%1,%2,%3};"
        : "+f"(c[0]), "+f"(c[1]), "+f"(c[2]), "+f"(c[3])
        : "r"(a[0]), "r"(a[1]), "r"(a[2]), "r"(a[3]), "r"(b[0]), "r"(b[1]));
}

// =================================================================
// Kernel 0: k_values [kf][c] -> KVT hi/lo [c][kf]
// =================================================================
__global__ void prep_kvt_kernel(const float* __restrict__ k_values) {
    int i = blockIdx.x * blockDim.x + threadIdx.x;
    if (i >= KF * CC) return;
    const int kf = i >> 6, c = i & 63;
    const float v = k_values[i];
    const __nv_bfloat16 hi = __float2bfloat16(v);
    g_KVThi[c * KF + kf] = hi;
    g_KVTlo[c * KF + kf] = __float2bfloat16(v - __bfloat162float(hi));
}

// =================================================================
// Kernel 1: Phase A -> WF (bf16 hi/lo), lane owns f = 2*lane, 2*lane+1
// =================================================================
#define WSM_ELEMS (TPB * HH * 16)
#define IDX_ELEMS (TPB * HH)
#define KP_ELEMS  (KK * 3)

__global__ void __launch_bounds__(THREADS_A)
phaseA_kernel(const float* __restrict__ points,
              const float* __restrict__ features,
              const float* __restrict__ output_points,
              const float* __restrict__ k_points,
              const int*   __restrict__ neighbor_indices)
{
    __shared__ float wsm[WSM_ELEMS];
    __shared__ int   idxs[IDX_ELEMS];
    __shared__ float kps[KP_ELEMS + 3];

    const int tid  = threadIdx.x;
    const int warp = tid >> 5;
    const int lane = tid & 31;

    if (tid < KP_ELEMS) kps[tid] = k_points[tid];
    __syncthreads();

    const int gp = blockIdx.x * TPB + warp;
    const int b  = gp >> 14;
    const float ox = output_points[gp * 3 + 0];
    const float oy = output_points[gp * 3 + 1];
    const float oz = output_points[gp * 3 + 2];

    const int nidx = neighbor_indices[gp * HH + lane];
    idxs[warp * HH + lane] = nidx;
    const float* pp = points + ((size_t)b * NN + nidx) * 3;
    const float rx = pp[0] - ox;
    const float ry = pp[1] - oy;
    const float rz = pp[2] - oz;

    float* wrow_mine = wsm + warp * (HH * 16) + lane * 16;
    #pragma unroll
    for (int k = 0; k < KK; k++) {
        const float dx = rx - kps[k * 3 + 0];
        const float dy = ry - kps[k * 3 + 1];
        const float dz = rz - kps[k * 3 + 2];
        const float d  = sqrtf(fmaf(dx, dx, fmaf(dy, dy, dz * dz)));
        wrow_mine[k] = fmaxf(1.0f - d, 0.0f);
    }
    wrow_mine[15] = 0.0f;
    __syncwarp();

    float acc0[KK], acc1[KK];
    #pragma unroll
    for (int k = 0; k < KK; k++) { acc0[k] = 0.0f; acc1[k] = 0.0f; }

    const float* fbase = features + (size_t)b * NN * FF;
    const int*   idxw  = idxs + warp * HH;
    const float* wbase = wsm + warp * (HH * 16);

    #pragma unroll 4
    for (int h = 0; h < HH; h++) {
        const int ni = idxw[h];
        const float2 fv = *(const float2*)(fbase + (size_t)ni * FF + 2 * lane);
        const float4 wA = *(const float4*)(wbase + h * 16 + 0);
        const float4 wB = *(const float4*)(wbase + h * 16 + 4);
        const float4 wC = *(const float4*)(wbase + h * 16 + 8);
        const float4 wD = *(const float4*)(wbase + h * 16 + 12);
        const float wv[15] = {wA.x, wA.y, wA.z, wA.w, wB.x, wB.y, wB.z, wB.w,
                              wC.x, wC.y, wC.z, wC.w, wD.x, wD.y, wD.z};
        #pragma unroll
        for (int k = 0; k < KK; k++) {
            acc0[k] = fmaf(wv[k], fv.x, acc0[k]);
            acc1[k] = fmaf(wv[k], fv.y, acc1[k]);
        }
    }

    __nv_bfloat162* whi = (__nv_bfloat162*)(g_WFhi + (size_t)gp * KF);
    __nv_bfloat162* wlo = (__nv_bfloat162*)(g_WFlo + (size_t)gp * KF);
    #pragma unroll
    for (int k = 0; k < KK; k++) {
        const __nv_bfloat162 h2 = __floats2bfloat162_rn(acc0[k], acc1[k]);
        whi[k * 32 + lane] = h2;
        const float l0 = acc0[k] - __low2float(h2);
        const float l1 = acc1[k] - __high2float(h2);
        wlo[k * 32 + lane] = __floats2bfloat162_rn(l0, l1);
    }
}

// =================================================================
// Kernel 2: out[p][c] via mma.sync m16n8k16 bf16, 3-term hi/lo
//   D[c16][p8] tiles: A = KVT[c][kf] (row-major), B = WF[p][kf] (k-contig cols)
// =================================================================
__global__ void __launch_bounds__(THREADS_G, 2)
gemm_kernel(float* __restrict__ out)
{
    extern __shared__ char smem[];
    const uint32_t smb = smem_u32(smem);

    const int tid  = threadIdx.x;
    const int wid  = tid >> 5;
    const int lane = tid & 31;
    const int g    = lane >> 2;   // group
    const int t    = lane & 3;    // thread-in-group
    const int m0   = blockIdx.x * PTS_CTA;
    const int pbase = wid * 32;   // warp's point offset within CTA

    float acc[4][4][4];           // [c-tile][p-tile][frag]
    #pragma unroll
    for (int i = 0; i < 4; i++)
        #pragma unroll
        for (int j = 0; j < 4; j++)
            #pragma unroll
            for (int q = 0; q < 4; q++) acc[i][j][q] = 0.0f;

    for (int ch = 0; ch < NCH; ch++) {
        __syncthreads();
        const size_t koff = (size_t)ch * KCH;
        // stage WF rows (hi & lo): 256 rows x 128B
        for (int u = tid; u < PTS_CTA * 8; u += THREADS_G) {
            const int r = u >> 3, s = u & 7;
            const size_t src = (size_t)(m0 + r) * KF + koff + s * 8;
            const uint32_t d = smb + OFF_WFHI + r * ROWB + s * 16;
            cpasync16(d, g_WFhi + src);
            cpasync16(d + (OFF_WFLO - OFF_WFHI), g_WFlo + src);
        }
        // stage KVT rows (hi & lo): 64 rows x 128B
        for (int u = tid; u < CC * 8; u += THREADS_G) {
            const int r = u >> 3, s = u & 7;
            const size_t src = (size_t)r * KF + koff + s * 8;
            const uint32_t d = smb + OFF_KVHI + r * ROWB + s * 16;
            cpasync16(d, g_KVThi + src);
            cpasync16(d + (OFF_KVLO - OFF_KVHI), g_KVTlo + src);
        }
        cpasync_commit();
        cpasync_wait0();
        __syncthreads();

        #pragma unroll
        for (int ks = 0; ks < KCH / 16; ks++) {
            const int kbB = ks * 32;   // byte offset of k-slice (16 bf16)

            // B frags (WF): 4 point-tiles
            uint32_t bh[4][2], bl[4][2];
            #pragma unroll
            for (int pt = 0; pt < 4; pt++) {
                const uint32_t rowoff = (pbase + pt * 8 + g) * ROWB + kbB + t * 4;
                bh[pt][0] = lds32(smb + OFF_WFHI + rowoff);
                bh[pt][1] = lds32(smb + OFF_WFHI + rowoff + 16);
                bl[pt][0] = lds32(smb + OFF_WFLO + rowoff);
                bl[pt][1] = lds32(smb + OFF_WFLO + rowoff + 16);
            }

            #pragma unroll
            for (int cm = 0; cm < 4; cm++) {
                const uint32_t rowoff = (cm * 16 + g) * ROWB + kbB + t * 4;
                uint32_t ah[4], al[4];
                ah[0] = lds32(smb + OFF_KVHI + rowoff);
                ah[1] = lds32(smb + OFF_KVHI + rowoff + 8 * ROWB);
                ah[2] = lds32(smb + OFF_KVHI + rowoff + 16);
                ah[3] = lds32(smb + OFF_KVHI + rowoff + 8 * ROWB + 16);
                al[0] = lds32(smb + OFF_KVLO + rowoff);
                al[1] = lds32(smb + OFF_KVLO + rowoff + 8 * ROWB);
                al[2] = lds32(smb + OFF_KVLO + rowoff + 16);
                al[3] = lds32(smb + OFF_KVLO + rowoff + 8 * ROWB + 16);

                #pragma unroll
                for (int pt = 0; pt < 4; pt++) {
                    mma16816(acc[cm][pt], ah, bh[pt]);   // hi*hi
                    mma16816(acc[cm][pt], ah, bl[pt]);   // hi*lo
                    mma16816(acc[cm][pt], al, bh[pt]);   // lo*hi
                }
            }
        }
    }

    // epilogue: D[c-row][p-col] -> out[p][c]
    #pragma unroll
    for (int cm = 0; cm < 4; cm++) {
        #pragma unroll
        for (int pt = 0; pt < 4; pt++) {
            const int c0 = cm * 16 + g;
            const int c1 = c0 + 8;
            const size_t p0 = (size_t)m0 + pbase + pt * 8 + t * 2;
            out[p0 * CC + c0]       = acc[cm][pt][0];
            out[(p0 + 1) * CC + c0] = acc[cm][pt][1];
            out[p0 * CC + c1]       = acc[cm][pt][2];
            out[(p0 + 1) * CC + c1] = acc[cm][pt][3];
        }
    }
}

// =================================================================
extern "C" void kernel_launch(void* const* d_in, const int* in_sizes, int n_in,
                              void* d_out, int out_size)
{
    const float* points        = (const float*)d_in[0];
    const float* features      = (const float*)d_in[1];
    const float* output_points = (const float*)d_in[2];
    const float* k_points      = (const float*)d_in[3];
    const float* k_values      = (const float*)d_in[4];
    const int*   neighbor_idx  = (const int*)d_in[5];
    float* out = (float*)d_out;

    static bool attr_done = false;
    if (!attr_done) {
        cudaFuncSetAttribute(gemm_kernel, cudaFuncAttributeMaxDynamicSharedMemorySize, SMEM_G);
        attr_done = true;
    }

    prep_kvt_kernel<<<(KF * CC + 255) / 256, 256>>>(k_values);
    phaseA_kernel<<<TOTALP / TPB, THREADS_A>>>(
        points, features, output_points, k_points, neighbor_idx);
    gemm_kernel<<<TOTALP / PTS_CTA, THREADS_G, SMEM_G>>>(out);
}